// round 1
// baseline (speedup 1.0000x reference)
#include <cuda_runtime.h>
#include <cuda_bf16.h>
#include <cstdint>

// Problem constants (fixed shapes from setup_inputs)
#define BATCH 32
#define SEQ   2048
#define DC    1024
#define H     512
#define MROWS (BATCH*SEQ)   // 65536
#define NEG_NUM -10000.0f

// Scratch (device globals; no allocation allowed)
__device__ float g_qb[BATCH * H];      // query @ Wq + b1
__device__ float g_score[MROWS];       // pre-softmax scores (atomic accum)

// ---------------------------------------------------------------------------
// helpers
// ---------------------------------------------------------------------------
__device__ __forceinline__ uint32_t f2tf32(float f) {
    uint32_t r;
    asm("cvt.rna.tf32.f32 %0, %1;" : "=r"(r) : "f"(f));
    return r;
}

__device__ __forceinline__ float fast_tanh(float x) {
    float y;
    asm("tanh.approx.f32 %0, %1;" : "=f"(y) : "f"(x));
    return y;
}

__device__ __forceinline__ void mma_tf32(float* c, const uint32_t* a, const uint32_t* b) {
    asm volatile(
        "mma.sync.aligned.m16n8k8.row.col.f32.tf32.tf32.f32 "
        "{%0,%1,%2,%3}, {%4,%5,%6,%7}, {%8,%9}, {%0,%1,%2,%3};"
        : "+f"(c[0]), "+f"(c[1]), "+f"(c[2]), "+f"(c[3])
        : "r"(a[0]), "r"(a[1]), "r"(a[2]), "r"(a[3]),
          "r"(b[0]), "r"(b[1]));
}

// ---------------------------------------------------------------------------
// Kernel 1: qb[b][h] = sum_d query[b][d] * W1[DC+d][h] + b1[h]
// grid(32), block(512)
// ---------------------------------------------------------------------------
__global__ void prep_kernel(const float* __restrict__ query,
                            const float* __restrict__ W1,
                            const float* __restrict__ b1) {
    int b = blockIdx.x;
    int h = threadIdx.x;            // 0..511
    __shared__ float sq[DC];
    for (int d = threadIdx.x; d < DC; d += blockDim.x)
        sq[d] = query[b * DC + d];
    __syncthreads();

    float acc = b1[h];
    #pragma unroll 4
    for (int d = 0; d < DC; d++)
        acc += sq[d] * W1[(size_t)(DC + d) * H + h];
    g_qb[b * H + h] = acc;
}

// ---------------------------------------------------------------------------
// Kernel 2: zero score + expected_ctx output region
// grid(64), block(1024)
// ---------------------------------------------------------------------------
__global__ void zero_kernel(float* __restrict__ out_ec) {
    int i = blockIdx.x * blockDim.x + threadIdx.x;
    if (i < MROWS) g_score[i] = 0.0f;
    if (i < BATCH * DC) out_ec[i] = 0.0f;
}

// ---------------------------------------------------------------------------
// Kernel 3: TF32 MMA GEMM (65536x1024 @ 1024x512) fused with
//           tanh(. + qb) * W2 row-reduction -> atomicAdd into g_score.
// Tiles: BM=128, BN=64, BK=32; 8 warps (2 m x 4 n); warp tile 64x16.
// grid(8 /*n*/, 512 /*m*/), block(256)
// ---------------------------------------------------------------------------
__global__ __launch_bounds__(256)
void gemm_kernel(const float* __restrict__ ctx,
                 const float* __restrict__ W1,
                 const float* __restrict__ W2) {
    const int n0   = blockIdx.x * 64;
    const int row0 = blockIdx.y * 128;
    const int b    = row0 >> 11;               // 2048 rows per batch, block never straddles
    const int tid  = threadIdx.x;
    const int warp = tid >> 5;
    const int lane = tid & 31;
    const int wm   = warp >> 2;                // 0..1
    const int wn   = warp & 3;                 // 0..3
    const int g    = lane >> 2;                // group id 0..7
    const int t    = lane & 3;                 // thread-in-group 0..3

    __shared__ uint32_t sA[128][36];           // padded: conflict-free fragment loads
    __shared__ uint32_t sB[64][36];            // sB[n][k] (transposed)

    float acc[4][2][4];
    #pragma unroll
    for (int mt = 0; mt < 4; mt++)
        #pragma unroll
        for (int nt = 0; nt < 2; nt++)
            #pragma unroll
            for (int j = 0; j < 4; j++)
                acc[mt][nt][j] = 0.0f;

    for (int kb = 0; kb < 32; kb++) {
        const int k0 = kb * 32;
        // --- load A tile (128x32) as float4, convert to tf32 ---
        #pragma unroll
        for (int i = 0; i < 4; i++) {
            int idx = tid + i * 256;           // 0..1023
            int r   = idx >> 3;
            int c4  = (idx & 7) << 2;
            float4 v = *(const float4*)(ctx + (size_t)(row0 + r) * DC + k0 + c4);
            uint4 u;
            u.x = f2tf32(v.x); u.y = f2tf32(v.y);
            u.z = f2tf32(v.z); u.w = f2tf32(v.w);
            *(uint4*)(&sA[r][c4]) = u;
        }
        // --- load B tile (32x64) transposed into sB[n][k] ---
        #pragma unroll
        for (int i = 0; i < 8; i++) {
            int idx = tid + i * 256;           // 0..2047
            int k   = idx >> 6;
            int n   = idx & 63;
            sB[n][k] = f2tf32(W1[(size_t)(k0 + k) * H + n0 + n]);
        }
        __syncthreads();

        #pragma unroll
        for (int ks = 0; ks < 4; ks++) {
            uint32_t af[4][4], bf[2][2];
            #pragma unroll
            for (int mt = 0; mt < 4; mt++) {
                int r = wm * 64 + mt * 16;
                af[mt][0] = sA[r + g][ks * 8 + t];
                af[mt][1] = sA[r + g + 8][ks * 8 + t];
                af[mt][2] = sA[r + g][ks * 8 + t + 4];
                af[mt][3] = sA[r + g + 8][ks * 8 + t + 4];
            }
            #pragma unroll
            for (int nt = 0; nt < 2; nt++) {
                int c = wn * 16 + nt * 8;
                bf[nt][0] = sB[c + g][ks * 8 + t];
                bf[nt][1] = sB[c + g][ks * 8 + t + 4];
            }
            #pragma unroll
            for (int mt = 0; mt < 4; mt++)
                #pragma unroll
                for (int nt = 0; nt < 2; nt++)
                    mma_tf32(acc[mt][nt], af[mt], bf[nt]);
        }
        __syncthreads();
    }

    // --- fused epilogue: score partial = sum_h W2[h]*tanh(acc + qb[b][h]) ---
    const int hbase = n0 + wn * 16;
    float w2v[2][2], qv[2][2];
    #pragma unroll
    for (int nt = 0; nt < 2; nt++)
        #pragma unroll
        for (int j = 0; j < 2; j++) {
            int h = hbase + nt * 8 + 2 * t + j;
            w2v[nt][j] = W2[h];
            qv[nt][j]  = g_qb[b * H + h];
        }

    #pragma unroll
    for (int mt = 0; mt < 4; mt++) {
        int r0 = row0 + wm * 64 + mt * 16 + g;
        float s0 = 0.0f, s1 = 0.0f;
        #pragma unroll
        for (int nt = 0; nt < 2; nt++) {
            #pragma unroll
            for (int j = 0; j < 2; j++) {
                s0 += fast_tanh(acc[mt][nt][j]     + qv[nt][j]) * w2v[nt][j];
                s1 += fast_tanh(acc[mt][nt][2 + j] + qv[nt][j]) * w2v[nt][j];
            }
        }
        // reduce across the 4 lanes of the group (t dimension)
        s0 += __shfl_xor_sync(0xffffffffu, s0, 1);
        s0 += __shfl_xor_sync(0xffffffffu, s0, 2);
        s1 += __shfl_xor_sync(0xffffffffu, s1, 1);
        s1 += __shfl_xor_sync(0xffffffffu, s1, 2);
        if (t == 0) {
            atomicAdd(&g_score[r0], s0);
            atomicAdd(&g_score[r0 + 8], s1);
        }
    }
}

// ---------------------------------------------------------------------------
// Kernel 4: masked softmax per batch row. grid(32), block(1024)
// ---------------------------------------------------------------------------
__global__ void softmax_kernel(const int* __restrict__ mask,
                               const float* __restrict__ b2,
                               float* __restrict__ p_out) {
    int b   = blockIdx.x;
    int tid = threadIdx.x;
    __shared__ float red[32];

    const float bias = b2[0];
    int i0 = b * SEQ + tid;
    int i1 = i0 + 1024;
    float s0 = (mask[i0] != 0) ? g_score[i0] + bias : NEG_NUM;
    float s1 = (mask[i1] != 0) ? g_score[i1] + bias : NEG_NUM;

    // --- max reduce ---
    float m = fmaxf(s0, s1);
    #pragma unroll
    for (int o = 16; o > 0; o >>= 1)
        m = fmaxf(m, __shfl_xor_sync(0xffffffffu, m, o));
    if ((tid & 31) == 0) red[tid >> 5] = m;
    __syncthreads();
    if (tid < 32) {
        float v = red[tid];
        #pragma unroll
        for (int o = 16; o > 0; o >>= 1)
            v = fmaxf(v, __shfl_xor_sync(0xffffffffu, v, o));
        red[tid] = v;
    }
    __syncthreads();
    m = red[0];
    __syncthreads();

    // --- exp + sum reduce ---
    float e0 = __expf(s0 - m);
    float e1 = __expf(s1 - m);
    float sm = e0 + e1;
    #pragma unroll
    for (int o = 16; o > 0; o >>= 1)
        sm += __shfl_xor_sync(0xffffffffu, sm, o);
    if ((tid & 31) == 0) red[tid >> 5] = sm;
    __syncthreads();
    if (tid < 32) {
        float v = red[tid];
        #pragma unroll
        for (int o = 16; o > 0; o >>= 1)
            v += __shfl_xor_sync(0xffffffffu, v, o);
        red[tid] = v;
    }
    __syncthreads();
    float inv = 1.0f / red[0];

    p_out[i0] = e0 * inv;
    p_out[i1] = e1 * inv;
}

// ---------------------------------------------------------------------------
// Kernel 5: expected_ctx[b][d] = sum_s p[b][s] * ctx[b][s][d]
// grid(32 /*b*/, 4 /*d-chunk 256*/, 4 /*s-chunk 512*/), block(256)
// ---------------------------------------------------------------------------
__global__ __launch_bounds__(256)
void wsum_kernel(const float* __restrict__ ctx,
                 const float* __restrict__ p,
                 float* __restrict__ out_ec) {
    int b  = blockIdx.x;
    int d  = blockIdx.y * 256 + threadIdx.x;
    int s0 = blockIdx.z * 512;

    __shared__ float sp[512];
    for (int i = threadIdx.x; i < 512; i += 256)
        sp[i] = p[b * SEQ + s0 + i];
    __syncthreads();

    const float* cptr = ctx + ((size_t)b * SEQ + s0) * DC + d;
    float acc = 0.0f;
    #pragma unroll 8
    for (int s = 0; s < 512; s++)
        acc += sp[s] * cptr[(size_t)s * DC];

    atomicAdd(&out_ec[b * DC + d], acc);
}

// ---------------------------------------------------------------------------
// launch
// ---------------------------------------------------------------------------
extern "C" void kernel_launch(void* const* d_in, const int* in_sizes, int n_in,
                              void* d_out, int out_size) {
    const float* ctx   = (const float*)d_in[0];
    const float* query = (const float*)d_in[1];
    const float* W1    = (const float*)d_in[2];
    const float* b1    = (const float*)d_in[3];
    const float* W2    = (const float*)d_in[4];
    const float* b2    = (const float*)d_in[5];
    const int*   mask  = (const int*)d_in[6];

    float* out    = (float*)d_out;
    float* out_ec = out;                    // expected_ctx: 32*1024
    float* out_p  = out + BATCH * DC;       // p_ctx:        32*2048

    prep_kernel<<<BATCH, 512>>>(query, W1, b1);
    zero_kernel<<<64, 1024>>>(out_ec);
    gemm_kernel<<<dim3(8, 512), 256>>>(ctx, W1, W2);
    softmax_kernel<<<BATCH, 1024>>>(mask, b2, out_p);
    wsum_kernel<<<dim3(BATCH, 4, 4), 256>>>(ctx, out_p, out_ec);
}

// round 3
// speedup vs baseline: 2.1091x; 2.1091x over previous
#include <cuda_runtime.h>
#include <cstdint>

#define BATCH 32
#define SEQ   2048
#define DC    1024
#define H     512
#define MROWS (BATCH*SEQ)
#define NEG_NUM -10000.0f

// ---------------------------------------------------------------------------
// device scratch
// ---------------------------------------------------------------------------
__device__ float g_qb[BATCH * H];                    // query @ Wq + b1
__device__ float g_score[MROWS];                     // pre-softmax scores
__device__ __align__(128) uint32_t g_Bt[H * DC];     // W1^T tf32, fragment-order
                                                     // [nb:4][kc:32][nblk:16][ks:4][lane:32][u:2]

// ---------------------------------------------------------------------------
// helpers
// ---------------------------------------------------------------------------
__device__ __forceinline__ uint32_t f2tf32(float f) {
    uint32_t r;
    asm("cvt.rna.tf32.f32 %0, %1;" : "=r"(r) : "f"(f));
    return r;
}
__device__ __forceinline__ float fast_tanh(float x) {
    float y;
    asm("tanh.approx.f32 %0, %1;" : "=f"(y) : "f"(x));
    return y;
}
__device__ __forceinline__ void mma_tf32(float* c, const uint32_t* a, const uint32_t* b) {
    asm volatile(
        "mma.sync.aligned.m16n8k8.row.col.f32.tf32.tf32.f32 "
        "{%0,%1,%2,%3}, {%4,%5,%6,%7}, {%8,%9}, {%0,%1,%2,%3};"
        : "+f"(c[0]), "+f"(c[1]), "+f"(c[2]), "+f"(c[3])
        : "r"(a[0]), "r"(a[1]), "r"(a[2]), "r"(a[3]),
          "r"(b[0]), "r"(b[1]));
}
__device__ __forceinline__ void cp_async16(uint32_t smem_dst, const void* gsrc) {
    asm volatile("cp.async.cg.shared.global [%0], [%1], 16;"
                 :: "r"(smem_dst), "l"(gsrc));
}
__device__ __forceinline__ void cp_commit() {
    asm volatile("cp.async.commit_group;");
}
template <int N>
__device__ __forceinline__ void cp_wait() {
    asm volatile("cp.async.wait_group %0;" :: "n"(N));
}

// ---------------------------------------------------------------------------
// Kernel 1: qb[b][h] = query[b] @ W1[DC:,h] + b1[h].  grid(32), block(512)
// ---------------------------------------------------------------------------
__global__ void prep_kernel(const float* __restrict__ query,
                            const float* __restrict__ W1,
                            const float* __restrict__ b1) {
    int b = blockIdx.x;
    int h = threadIdx.x;
    __shared__ float sq[DC];
    for (int d = threadIdx.x; d < DC; d += blockDim.x)
        sq[d] = query[b * DC + d];
    __syncthreads();
    float acc = b1[h];
    #pragma unroll 4
    for (int d = 0; d < DC; d++)
        acc += sq[d] * W1[(size_t)(DC + d) * H + h];
    g_qb[b * H + h] = acc;
}

// ---------------------------------------------------------------------------
// Kernel 1b: W1[:DC] -> g_Bt in fragment order (tf32, RNA-rounded).
// word index id encodes: ((((nb*32+kc)*16+nblk)*4+ks)*32 + g*4+t)*2 + u
// value = W1[k*H + n], n = nb*128+nblk*8+g, k = kc*32+ks*8+u*4+t.
// grid(512), block(1024)
// ---------------------------------------------------------------------------
__global__ void prepb_kernel(const float* __restrict__ W1) {
    int id = blockIdx.x * 1024 + threadIdx.x;   // 0..524287
    int u    = id & 1;
    int tmp  = id >> 1;
    int g    = (tmp >> 2) & 7;
    int t    = tmp & 3;
    tmp >>= 5;
    int ks   = tmp & 3;  tmp >>= 2;
    int nblk = tmp & 15; tmp >>= 4;
    int kc   = tmp & 31; tmp >>= 5;
    int nb   = tmp;
    int n = nb * 128 + nblk * 8 + g;
    int k = kc * 32 + ks * 8 + u * 4 + t;
    g_Bt[id] = f2tf32(W1[(size_t)k * H + n]);
}

// ---------------------------------------------------------------------------
// Kernel 2: zero g_score + expected_ctx.  grid(64), block(1024)
// ---------------------------------------------------------------------------
__global__ void zero_kernel(float* __restrict__ out_ec) {
    int i = blockIdx.x * blockDim.x + threadIdx.x;
    if (i < MROWS) g_score[i] = 0.0f;
    if (i < BATCH * DC) out_ec[i] = 0.0f;
}

// ---------------------------------------------------------------------------
// Kernel 3: TF32 mma.sync GEMM, BM=128 BN=128 BK=32, 8 warps (2x4),
// warp tile 64x32, 3-stage cp.async pipeline, fused tanh*W2 epilogue.
// grid(4 /*n*/, 512 /*m*/), block(256)
// ---------------------------------------------------------------------------
#define A_WORDS (128*36)               // padded rows: conflict-free frag loads
#define B_WORDS (128*32)               // fragment-order
#define STAGE_WORDS (A_WORDS + B_WORDS)
#define NSTAGE 3
#define SMEM_DYN (STAGE_WORDS * NSTAGE * 4)

__global__ __launch_bounds__(256, 1)
void gemm_kernel(const float* __restrict__ ctx,
                 const float* __restrict__ W2) {
    extern __shared__ uint32_t smem[];
    __shared__ float s_qb[128];
    __shared__ float s_w2[128];

    const int n0   = blockIdx.x * 128;
    const int row0 = blockIdx.y * 128;
    const int b    = row0 >> 11;
    const int tid  = threadIdx.x;
    const int warp = tid >> 5;
    const int lane = tid & 31;
    const int wm   = warp >> 2;          // 0..1  (64 rows each)
    const int wn   = warp & 3;           // 0..3  (32 cols each)
    const int g    = lane >> 2;
    const int t    = lane & 3;

    if (tid < 128) {
        s_qb[tid] = g_qb[b * H + n0 + tid];
        s_w2[tid] = W2[n0 + tid];
    }

    const uint32_t smem_base = (uint32_t)__cvta_generic_to_shared(smem);

    // ---- cp.async issue for one k-chunk into stage s ----
    auto issue = [&](int kc, int s) {
        uint32_t aBase = smem_base + (uint32_t)(s * STAGE_WORDS) * 4u;
        uint32_t bBase = aBase + A_WORDS * 4u;
        // A: 128 rows x 8 quads (16B each) = 1024 chunks, 4 per thread
        const float* asrc = ctx + (size_t)row0 * DC + kc * 32;
        #pragma unroll
        for (int j = 0; j < 4; j++) {
            int idx = tid + j * 256;       // 0..1023
            int m   = idx >> 3;
            int c   = idx & 7;
            cp_async16(aBase + (uint32_t)(m * 36 + c * 4) * 4u,
                       asrc + (size_t)m * DC + c * 4);
        }
        // B: 16KB = 1024 chunks of 16B, contiguous copy from fragment-order global
        const uint32_t* bsrc = g_Bt + ((size_t)blockIdx.x * 32 + kc) * B_WORDS;
        #pragma unroll
        for (int j = 0; j < 4; j++) {
            int idx = tid + j * 256;
            cp_async16(bBase + (uint32_t)idx * 16u, bsrc + idx * 4);
        }
    };

    float acc[4][4][4];
    #pragma unroll
    for (int mt = 0; mt < 4; mt++)
        #pragma unroll
        for (int nt = 0; nt < 4; nt++)
            #pragma unroll
            for (int j = 0; j < 4; j++)
                acc[mt][nt][j] = 0.0f;

    // prologue: fill 3 stages
    issue(0, 0); cp_commit();
    issue(1, 1); cp_commit();
    issue(2, 2); cp_commit();

    for (int kc = 0; kc < 32; kc++) {
        const int s = kc % NSTAGE;
        cp_wait<2>();                   // stage s data ready
        __syncthreads();

        const uint32_t* sA = smem + s * STAGE_WORDS;
        const uint32_t* sB = sA + A_WORDS;

        #pragma unroll
        for (int ks = 0; ks < 4; ks++) {
            uint32_t af[4][4];
            #pragma unroll
            for (int mt = 0; mt < 4; mt++) {
                int r = wm * 64 + mt * 16;
                const uint32_t* base = sA + (size_t)(r + g) * 36 + ks * 8 + t;
                af[mt][0] = base[0];
                af[mt][2] = base[4];
                af[mt][1] = base[8 * 36];
                af[mt][3] = base[8 * 36 + 4];
            }
            uint32_t bf[4][2];
            #pragma unroll
            for (int nt = 0; nt < 4; nt++) {
                int nblk = wn * 4 + nt;
                const uint2 v = *(const uint2*)(sB + ((nblk * 4 + ks) * 32 + lane) * 2);
                bf[nt][0] = v.x;
                bf[nt][1] = v.y;
            }
            #pragma unroll
            for (int mt = 0; mt < 4; mt++)
                #pragma unroll
                for (int nt = 0; nt < 4; nt++)
                    mma_tf32(acc[mt][nt], af[mt], bf[nt]);
        }

        __syncthreads();                // all warps done reading stage s
        if (kc + NSTAGE < 32) issue(kc + NSTAGE, s);
        cp_commit();                    // commit every iter (may be empty)
    }

    // --- fused epilogue: g_score[r] += sum_h W2[h]*tanh(acc + qb[h]) ---
    float w2v[4][2], qv[4][2];
    #pragma unroll
    for (int nt = 0; nt < 4; nt++)
        #pragma unroll
        for (int j = 0; j < 2; j++) {
            int hl = wn * 32 + nt * 8 + 2 * t + j;
            w2v[nt][j] = s_w2[hl];
            qv[nt][j]  = s_qb[hl];
        }

    #pragma unroll
    for (int mt = 0; mt < 4; mt++) {
        int r0 = row0 + wm * 64 + mt * 16 + g;
        float s0 = 0.0f, s1 = 0.0f;
        #pragma unroll
        for (int nt = 0; nt < 4; nt++) {
            #pragma unroll
            for (int j = 0; j < 2; j++) {
                s0 += fast_tanh(acc[mt][nt][j]     + qv[nt][j]) * w2v[nt][j];
                s1 += fast_tanh(acc[mt][nt][2 + j] + qv[nt][j]) * w2v[nt][j];
            }
        }
        s0 += __shfl_xor_sync(0xffffffffu, s0, 1);
        s0 += __shfl_xor_sync(0xffffffffu, s0, 2);
        s1 += __shfl_xor_sync(0xffffffffu, s1, 1);
        s1 += __shfl_xor_sync(0xffffffffu, s1, 2);
        if (t == 0) {
            atomicAdd(&g_score[r0], s0);
            atomicAdd(&g_score[r0 + 8], s1);
        }
    }
}

// ---------------------------------------------------------------------------
// Kernel 4: masked softmax per batch row. grid(32), block(1024)
// ---------------------------------------------------------------------------
__global__ void softmax_kernel(const int* __restrict__ mask,
                               const float* __restrict__ b2,
                               float* __restrict__ p_out) {
    int b   = blockIdx.x;
    int tid = threadIdx.x;
    __shared__ float red[32];

    const float bias = b2[0];
    int i0 = b * SEQ + tid;
    int i1 = i0 + 1024;
    float s0 = (mask[i0] != 0) ? g_score[i0] + bias : NEG_NUM;
    float s1 = (mask[i1] != 0) ? g_score[i1] + bias : NEG_NUM;

    float m = fmaxf(s0, s1);
    #pragma unroll
    for (int o = 16; o > 0; o >>= 1)
        m = fmaxf(m, __shfl_xor_sync(0xffffffffu, m, o));
    if ((tid & 31) == 0) red[tid >> 5] = m;
    __syncthreads();
    if (tid < 32) {
        float v = red[tid];
        #pragma unroll
        for (int o = 16; o > 0; o >>= 1)
            v = fmaxf(v, __shfl_xor_sync(0xffffffffu, v, o));
        red[tid] = v;
    }
    __syncthreads();
    m = red[0];
    __syncthreads();

    float e0 = __expf(s0 - m);
    float e1 = __expf(s1 - m);
    float sm = e0 + e1;
    #pragma unroll
    for (int o = 16; o > 0; o >>= 1)
        sm += __shfl_xor_sync(0xffffffffu, sm, o);
    if ((tid & 31) == 0) red[tid >> 5] = sm;
    __syncthreads();
    if (tid < 32) {
        float v = red[tid];
        #pragma unroll
        for (int o = 16; o > 0; o >>= 1)
            v += __shfl_xor_sync(0xffffffffu, v, o);
        red[tid] = v;
    }
    __syncthreads();
    float inv = 1.0f / red[0];

    p_out[i0] = e0 * inv;
    p_out[i1] = e1 * inv;
}

// ---------------------------------------------------------------------------
// Kernel 5: expected_ctx[b][d] = sum_s p[b][s]*ctx[b][s][d]
// grid(32,4,4), block(256)
// ---------------------------------------------------------------------------
__global__ __launch_bounds__(256)
void wsum_kernel(const float* __restrict__ ctx,
                 const float* __restrict__ p,
                 float* __restrict__ out_ec) {
    int b  = blockIdx.x;
    int d  = blockIdx.y * 256 + threadIdx.x;
    int s0 = blockIdx.z * 512;

    __shared__ float sp[512];
    for (int i = threadIdx.x; i < 512; i += 256)
        sp[i] = p[b * SEQ + s0 + i];
    __syncthreads();

    const float* cptr = ctx + ((size_t)b * SEQ + s0) * DC + d;
    float acc = 0.0f;
    #pragma unroll 8
    for (int s = 0; s < 512; s++)
        acc += sp[s] * cptr[(size_t)s * DC];

    atomicAdd(&out_ec[b * DC + d], acc);
}

// ---------------------------------------------------------------------------
// launch
// ---------------------------------------------------------------------------
extern "C" void kernel_launch(void* const* d_in, const int* in_sizes, int n_in,
                              void* d_out, int out_size) {
    const float* ctx   = (const float*)d_in[0];
    const float* query = (const float*)d_in[1];
    const float* W1    = (const float*)d_in[2];
    const float* b1    = (const float*)d_in[3];
    const float* W2    = (const float*)d_in[4];
    const float* b2    = (const float*)d_in[5];
    const int*   mask  = (const int*)d_in[6];

    float* out    = (float*)d_out;
    float* out_ec = out;
    float* out_p  = out + BATCH * DC;

    static bool attr_set = false;
    if (!attr_set) {
        cudaFuncSetAttribute(gemm_kernel,
                             cudaFuncAttributeMaxDynamicSharedMemorySize, SMEM_DYN);
        attr_set = true;
    }

    prep_kernel<<<BATCH, 512>>>(query, W1, b1);
    prepb_kernel<<<512, 1024>>>(W1);
    zero_kernel<<<64, 1024>>>(out_ec);
    gemm_kernel<<<dim3(4, 512), 256, SMEM_DYN>>>(ctx, W2);
    softmax_kernel<<<BATCH, 1024>>>(mask, b2, out_p);
    wsum_kernel<<<dim3(BATCH, 4, 4), 256>>>(ctx, out_p, out_ec);
}

// round 4
// speedup vs baseline: 2.1608x; 1.0245x over previous
#include <cuda_runtime.h>
#include <cstdint>

#define BATCH 32
#define SEQ   2048
#define DC    1024
#define H     512
#define MROWS (BATCH*SEQ)
#define NEG_NUM -10000.0f

// ---------------------------------------------------------------------------
// device scratch
// ---------------------------------------------------------------------------
__device__ float g_qb[BATCH * H];                    // query @ Wq + b1
__device__ float g_score[MROWS];                     // pre-softmax scores
__device__ __align__(128) uint32_t g_Bt[H * DC];     // W1^T tf32, fragment-order

// ---------------------------------------------------------------------------
// helpers
// ---------------------------------------------------------------------------
__device__ __forceinline__ uint32_t f2tf32(float f) {
    uint32_t r;
    asm("cvt.rna.tf32.f32 %0, %1;" : "=r"(r) : "f"(f));
    return r;
}
__device__ __forceinline__ float fast_tanh(float x) {
    float y;
    asm("tanh.approx.f32 %0, %1;" : "=f"(y) : "f"(x));
    return y;
}
__device__ __forceinline__ void mma_tf32(float* c, const uint32_t* a, const uint32_t* b) {
    asm volatile(
        "mma.sync.aligned.m16n8k8.row.col.f32.tf32.tf32.f32 "
        "{%0,%1,%2,%3}, {%4,%5,%6,%7}, {%8,%9}, {%0,%1,%2,%3};"
        : "+f"(c[0]), "+f"(c[1]), "+f"(c[2]), "+f"(c[3])
        : "r"(a[0]), "r"(a[1]), "r"(a[2]), "r"(a[3]),
          "r"(b[0]), "r"(b[1]));
}
__device__ __forceinline__ void cp_async16(uint32_t smem_dst, const void* gsrc) {
    asm volatile("cp.async.cg.shared.global [%0], [%1], 16;"
                 :: "r"(smem_dst), "l"(gsrc));
}
__device__ __forceinline__ void cp_commit() {
    asm volatile("cp.async.commit_group;");
}
template <int N>
__device__ __forceinline__ void cp_wait() {
    asm volatile("cp.async.wait_group %0;" :: "n"(N));
}

// ---------------------------------------------------------------------------
// Kernel 1: qb[b][h] = query[b] @ W1[DC:,h] + b1[h].  grid(32), block(512)
// ---------------------------------------------------------------------------
__global__ void prep_kernel(const float* __restrict__ query,
                            const float* __restrict__ W1,
                            const float* __restrict__ b1) {
    int b = blockIdx.x;
    int h = threadIdx.x;
    __shared__ float sq[DC];
    for (int d = threadIdx.x; d < DC; d += blockDim.x)
        sq[d] = query[b * DC + d];
    __syncthreads();
    float acc = b1[h];
    #pragma unroll 4
    for (int d = 0; d < DC; d++)
        acc += sq[d] * W1[(size_t)(DC + d) * H + h];
    g_qb[b * H + h] = acc;
}

// ---------------------------------------------------------------------------
// Kernel 1b: W1[:DC] -> g_Bt in fragment order (tf32, RNA-rounded).
// word id = ((((nb*32+kc)*16+nblk)*4+ks)*32 + g*4+t)*2 + u
// value  = W1[k*H + n],  n = nb*128+nblk*8+g,  k = kc*32+ks*8+u*4+t.
// ---------------------------------------------------------------------------
__global__ void prepb_kernel(const float* __restrict__ W1) {
    int id = blockIdx.x * 1024 + threadIdx.x;   // 0..524287
    int u    = id & 1;
    int tmp  = id >> 1;
    int g    = (tmp >> 2) & 7;
    int t    = tmp & 3;
    tmp >>= 5;
    int ks   = tmp & 3;  tmp >>= 2;
    int nblk = tmp & 15; tmp >>= 4;
    int kc   = tmp & 31; tmp >>= 5;
    int nb   = tmp;
    int n = nb * 128 + nblk * 8 + g;
    int k = kc * 32 + ks * 8 + u * 4 + t;
    g_Bt[id] = f2tf32(W1[(size_t)k * H + n]);
}

// ---------------------------------------------------------------------------
// Kernel 2: zero g_score + expected_ctx.  grid(64), block(1024)
// ---------------------------------------------------------------------------
__global__ void zero_kernel(float* __restrict__ out_ec) {
    int i = blockIdx.x * blockDim.x + threadIdx.x;
    if (i < MROWS) g_score[i] = 0.0f;
    if (i < BATCH * DC) out_ec[i] = 0.0f;
}

// ---------------------------------------------------------------------------
// Kernel 3: TF32 mma.sync GEMM, BM=128 BN=128 BK=32, 8 warps (2x4),
// warp tile 64x32, 4-stage cp.async pipeline (single barrier per tile),
// register-double-buffered fragments, fused tanh*W2 epilogue.
// grid(4 /*n*/, 512 /*m*/), block(256)
// ---------------------------------------------------------------------------
#define A_WORDS (128*36)
#define B_WORDS (128*32)
#define STAGE_WORDS (A_WORDS + B_WORDS)
#define NSTAGE 4
#define SMEM_DYN (STAGE_WORDS * NSTAGE * 4)

__global__ __launch_bounds__(256, 1)
void gemm_kernel(const float* __restrict__ ctx,
                 const float* __restrict__ W2) {
    extern __shared__ uint32_t smem[];
    __shared__ float s_qb[128];
    __shared__ float s_w2[128];

    const int n0   = blockIdx.x * 128;
    const int row0 = blockIdx.y * 128;
    const int b    = row0 >> 11;
    const int tid  = threadIdx.x;
    const int warp = tid >> 5;
    const int lane = tid & 31;
    const int wm   = warp >> 2;          // 0..1  (64 rows)
    const int wn   = warp & 3;           // 0..3  (32 cols)
    const int g    = lane >> 2;
    const int t    = lane & 3;

    if (tid < 128) {
        s_qb[tid] = g_qb[b * H + n0 + tid];
        s_w2[tid] = W2[n0 + tid];
    }

    const uint32_t smem_base = (uint32_t)__cvta_generic_to_shared(smem);

    auto issue = [&](int kc, int s) {
        uint32_t aBase = smem_base + (uint32_t)(s * STAGE_WORDS) * 4u;
        uint32_t bBase = aBase + A_WORDS * 4u;
        const float* asrc = ctx + (size_t)row0 * DC + kc * 32;
        #pragma unroll
        for (int j = 0; j < 4; j++) {
            int idx = tid + j * 256;
            int m   = idx >> 3;
            int c   = idx & 7;
            cp_async16(aBase + (uint32_t)(m * 36 + c * 4) * 4u,
                       asrc + (size_t)m * DC + c * 4);
        }
        const uint32_t* bsrc = g_Bt + ((size_t)blockIdx.x * 32 + kc) * B_WORDS;
        #pragma unroll
        for (int j = 0; j < 4; j++) {
            int idx = tid + j * 256;
            cp_async16(bBase + (uint32_t)idx * 16u, bsrc + idx * 4);
        }
    };

    float acc[4][4][4];
    #pragma unroll
    for (int mt = 0; mt < 4; mt++)
        #pragma unroll
        for (int nt = 0; nt < 4; nt++)
            #pragma unroll
            for (int j = 0; j < 4; j++)
                acc[mt][nt][j] = 0.0f;

    // prologue: fill NSTAGE-1 stages
    issue(0, 0); cp_commit();
    issue(1, 1); cp_commit();
    issue(2, 2); cp_commit();

    // fragment loader (ks given) from stage pointers
    const int aoff = (wm * 64 + g) * 36 + t;      // + mt*16*36 + ks*8 (+4)
    const int boff = (wn * 4 * 4) * 64 + lane * 2; // + nt*4*64 + ks*64

    for (int kc = 0; kc < 32; kc++) {
        const int s = kc & (NSTAGE - 1);
        cp_wait<NSTAGE - 2>();          // stage s ready
        __syncthreads();

        // issue next stage (slot was fully read at iter kc-1, fenced above)
        if (kc + NSTAGE - 1 < 32) issue(kc + NSTAGE - 1, (kc + NSTAGE - 1) & (NSTAGE - 1));
        cp_commit();

        const uint32_t* sA = smem + s * STAGE_WORDS;
        const uint32_t* sB = sA + A_WORDS;

        uint32_t af[2][4][4], bf[2][4][2];
        // preload ks=0 fragments
        #pragma unroll
        for (int mt = 0; mt < 4; mt++) {
            const uint32_t* base = sA + aoff + mt * 16 * 36;
            af[0][mt][0] = base[0];
            af[0][mt][2] = base[4];
            af[0][mt][1] = base[8 * 36];
            af[0][mt][3] = base[8 * 36 + 4];
        }
        #pragma unroll
        for (int nt = 0; nt < 4; nt++) {
            const uint2 v = *(const uint2*)(sB + boff + nt * 4 * 64);
            bf[0][nt][0] = v.x;
            bf[0][nt][1] = v.y;
        }

        #pragma unroll
        for (int ks = 0; ks < 4; ks++) {
            const int cur = ks & 1;
            const int nxt = cur ^ 1;
            if (ks < 3) {
                #pragma unroll
                for (int mt = 0; mt < 4; mt++) {
                    const uint32_t* base = sA + aoff + mt * 16 * 36 + (ks + 1) * 8;
                    af[nxt][mt][0] = base[0];
                    af[nxt][mt][2] = base[4];
                    af[nxt][mt][1] = base[8 * 36];
                    af[nxt][mt][3] = base[8 * 36 + 4];
                }
                #pragma unroll
                for (int nt = 0; nt < 4; nt++) {
                    const uint2 v = *(const uint2*)(sB + boff + nt * 4 * 64 + (ks + 1) * 64);
                    bf[nxt][nt][0] = v.x;
                    bf[nxt][nt][1] = v.y;
                }
            }
            #pragma unroll
            for (int mt = 0; mt < 4; mt++)
                #pragma unroll
                for (int nt = 0; nt < 4; nt++)
                    mma_tf32(acc[mt][nt], af[cur][mt], bf[cur][nt]);
        }
    }

    // --- fused epilogue: g_score[r] += sum_h W2[h]*tanh(acc + qb[h]) ---
    float w2v[4][2], qv[4][2];
    #pragma unroll
    for (int nt = 0; nt < 4; nt++)
        #pragma unroll
        for (int j = 0; j < 2; j++) {
            int hl = wn * 32 + nt * 8 + 2 * t + j;
            w2v[nt][j] = s_w2[hl];
            qv[nt][j]  = s_qb[hl];
        }

    #pragma unroll
    for (int mt = 0; mt < 4; mt++) {
        int r0 = row0 + wm * 64 + mt * 16 + g;
        float s0 = 0.0f, s1 = 0.0f;
        #pragma unroll
        for (int nt = 0; nt < 4; nt++) {
            #pragma unroll
            for (int j = 0; j < 2; j++) {
                s0 += fast_tanh(acc[mt][nt][j]     + qv[nt][j]) * w2v[nt][j];
                s1 += fast_tanh(acc[mt][nt][2 + j] + qv[nt][j]) * w2v[nt][j];
            }
        }
        s0 += __shfl_xor_sync(0xffffffffu, s0, 1);
        s0 += __shfl_xor_sync(0xffffffffu, s0, 2);
        s1 += __shfl_xor_sync(0xffffffffu, s1, 1);
        s1 += __shfl_xor_sync(0xffffffffu, s1, 2);
        if (t == 0) {
            atomicAdd(&g_score[r0], s0);
            atomicAdd(&g_score[r0 + 8], s1);
        }
    }
}

// ---------------------------------------------------------------------------
// Kernel 4: masked softmax per batch row. grid(32), block(1024)
// ---------------------------------------------------------------------------
__global__ void softmax_kernel(const int* __restrict__ mask,
                               const float* __restrict__ b2,
                               float* __restrict__ p_out) {
    int b   = blockIdx.x;
    int tid = threadIdx.x;
    __shared__ float red[32];

    const float bias = b2[0];
    int i0 = b * SEQ + tid;
    int i1 = i0 + 1024;
    float s0 = (mask[i0] != 0) ? g_score[i0] + bias : NEG_NUM;
    float s1 = (mask[i1] != 0) ? g_score[i1] + bias : NEG_NUM;

    float m = fmaxf(s0, s1);
    #pragma unroll
    for (int o = 16; o > 0; o >>= 1)
        m = fmaxf(m, __shfl_xor_sync(0xffffffffu, m, o));
    if ((tid & 31) == 0) red[tid >> 5] = m;
    __syncthreads();
    if (tid < 32) {
        float v = red[tid];
        #pragma unroll
        for (int o = 16; o > 0; o >>= 1)
            v = fmaxf(v, __shfl_xor_sync(0xffffffffu, v, o));
        red[tid] = v;
    }
    __syncthreads();
    m = red[0];
    __syncthreads();

    float e0 = __expf(s0 - m);
    float e1 = __expf(s1 - m);
    float sm = e0 + e1;
    #pragma unroll
    for (int o = 16; o > 0; o >>= 1)
        sm += __shfl_xor_sync(0xffffffffu, sm, o);
    if ((tid & 31) == 0) red[tid >> 5] = sm;
    __syncthreads();
    if (tid < 32) {
        float v = red[tid];
        #pragma unroll
        for (int o = 16; o > 0; o >>= 1)
            v += __shfl_xor_sync(0xffffffffu, v, o);
        red[tid] = v;
    }
    __syncthreads();
    float inv = 1.0f / red[0];

    p_out[i0] = e0 * inv;
    p_out[i1] = e1 * inv;
}

// ---------------------------------------------------------------------------
// Kernel 5: expected_ctx[b][d] = sum_s p[b][s]*ctx[b][s][d]
// grid(32,4,8), block(256)
// ---------------------------------------------------------------------------
__global__ __launch_bounds__(256)
void wsum_kernel(const float* __restrict__ ctx,
                 const float* __restrict__ p,
                 float* __restrict__ out_ec) {
    int b  = blockIdx.x;
    int d  = blockIdx.y * 256 + threadIdx.x;
    int s0 = blockIdx.z * 256;

    __shared__ float sp[256];
    if (threadIdx.x < 256)
        sp[threadIdx.x] = p[b * SEQ + s0 + threadIdx.x];
    __syncthreads();

    const float* cptr = ctx + ((size_t)b * SEQ + s0) * DC + d;
    float acc = 0.0f;
    #pragma unroll 8
    for (int s = 0; s < 256; s++)
        acc += sp[s] * cptr[(size_t)s * DC];

    atomicAdd(&out_ec[b * DC + d], acc);
}

// ---------------------------------------------------------------------------
// launch
// ---------------------------------------------------------------------------
extern "C" void kernel_launch(void* const* d_in, const int* in_sizes, int n_in,
                              void* d_out, int out_size) {
    const float* ctx   = (const float*)d_in[0];
    const float* query = (const float*)d_in[1];
    const float* W1    = (const float*)d_in[2];
    const float* b1    = (const float*)d_in[3];
    const float* W2    = (const float*)d_in[4];
    const float* b2    = (const float*)d_in[5];
    const int*   mask  = (const int*)d_in[6];

    float* out    = (float*)d_out;
    float* out_ec = out;
    float* out_p  = out + BATCH * DC;

    static bool attr_set = false;
    if (!attr_set) {
        cudaFuncSetAttribute(gemm_kernel,
                             cudaFuncAttributeMaxDynamicSharedMemorySize, SMEM_DYN);
        attr_set = true;
    }

    prep_kernel<<<BATCH, 512>>>(query, W1, b1);
    prepb_kernel<<<512, 1024>>>(W1);
    zero_kernel<<<64, 1024>>>(out_ec);
    gemm_kernel<<<dim3(4, 512), 256, SMEM_DYN>>>(ctx, W2);
    softmax_kernel<<<BATCH, 1024>>>(mask, b2, out_p);
    wsum_kernel<<<dim3(BATCH, 4, 8), 256>>>(ctx, out_p, out_ec);
}

// round 5
// speedup vs baseline: 3.3721x; 1.5606x over previous
#include <cuda_runtime.h>
#include <cstdint>

#define BATCH 32
#define SEQ   2048
#define DC    1024
#define H     512
#define MROWS (BATCH*SEQ)
#define NEG_NUM -10000.0f

// ---------------------------------------------------------------------------
// device scratch
// ---------------------------------------------------------------------------
__device__ float g_qb[BATCH * H];                    // query @ Wq + b1
__device__ float g_score[MROWS];                     // pre-softmax scores
__device__ __align__(128) uint32_t g_Bt[H * DC];     // W1^T tf32, fragment-order
__device__ int g_rowidx[MROWS];                      // per-batch compacted row indices
__device__ int g_count[BATCH];                       // per-batch masked-in count

// ---------------------------------------------------------------------------
// helpers
// ---------------------------------------------------------------------------
__device__ __forceinline__ uint32_t f2tf32(float f) {
    uint32_t r;
    asm("cvt.rna.tf32.f32 %0, %1;" : "=r"(r) : "f"(f));
    return r;
}
__device__ __forceinline__ float fast_tanh(float x) {
    float y;
    asm("tanh.approx.f32 %0, %1;" : "=f"(y) : "f"(x));
    return y;
}
__device__ __forceinline__ void mma_tf32(float* c, const uint32_t* a, const uint32_t* b) {
    asm volatile(
        "mma.sync.aligned.m16n8k8.row.col.f32.tf32.tf32.f32 "
        "{%0,%1,%2,%3}, {%4,%5,%6,%7}, {%8,%9}, {%0,%1,%2,%3};"
        : "+f"(c[0]), "+f"(c[1]), "+f"(c[2]), "+f"(c[3])
        : "r"(a[0]), "r"(a[1]), "r"(a[2]), "r"(a[3]),
          "r"(b[0]), "r"(b[1]));
}
__device__ __forceinline__ void cp_async16(uint32_t smem_dst, const void* gsrc) {
    asm volatile("cp.async.cg.shared.global [%0], [%1], 16;"
                 :: "r"(smem_dst), "l"(gsrc));
}
__device__ __forceinline__ void cp_commit() {
    asm volatile("cp.async.commit_group;");
}
template <int N>
__device__ __forceinline__ void cp_wait() {
    asm volatile("cp.async.wait_group %0;" :: "n"(N));
}

// ---------------------------------------------------------------------------
// Kernel 1: qb[b][h] = query[b] @ W1[DC:,h] + b1[h].  grid(32), block(512)
// ---------------------------------------------------------------------------
__global__ void prep_kernel(const float* __restrict__ query,
                            const float* __restrict__ W1,
                            const float* __restrict__ b1) {
    int b = blockIdx.x;
    int h = threadIdx.x;
    __shared__ float sq[DC];
    for (int d = threadIdx.x; d < DC; d += blockDim.x)
        sq[d] = query[b * DC + d];
    __syncthreads();
    float acc = b1[h];
    #pragma unroll 4
    for (int d = 0; d < DC; d++)
        acc += sq[d] * W1[(size_t)(DC + d) * H + h];
    g_qb[b * H + h] = acc;
}

// ---------------------------------------------------------------------------
// Kernel 1b: W1[:DC] -> g_Bt in fragment order (tf32, RNA-rounded).
// word id = ((((nb*32+kc)*16+nblk)*4+ks)*32 + g*4+t)*2 + u
// value  = W1[k*H + n],  n = nb*128+nblk*8+g,  k = kc*32+ks*8+u*4+t.
// ---------------------------------------------------------------------------
__global__ void prepb_kernel(const float* __restrict__ W1) {
    int id = blockIdx.x * 1024 + threadIdx.x;   // 0..524287
    int u    = id & 1;
    int tmp  = id >> 1;
    int g    = (tmp >> 2) & 7;
    int t    = tmp & 3;
    tmp >>= 5;
    int ks   = tmp & 3;  tmp >>= 2;
    int nblk = tmp & 15; tmp >>= 4;
    int kc   = tmp & 31; tmp >>= 5;
    int nb   = tmp;
    int n = nb * 128 + nblk * 8 + g;
    int k = kc * 32 + ks * 8 + u * 4 + t;
    g_Bt[id] = f2tf32(W1[(size_t)k * H + n]);
}

// ---------------------------------------------------------------------------
// Kernel 1c: stable compaction of mask=1 rows per batch.
// grid(32), block(1024); thread t handles seq 2t, 2t+1.
// ---------------------------------------------------------------------------
__global__ void mask_scan_kernel(const int* __restrict__ mask) {
    int b = blockIdx.x;
    int t = threadIdx.x;
    int lane = t & 31, warp = t >> 5;
    int s0 = 2 * t, s1 = 2 * t + 1;
    int v0 = (mask[b * SEQ + s0] != 0) ? 1 : 0;
    int v1 = (mask[b * SEQ + s1] != 0) ? 1 : 0;
    int loc = v0 + v1;

    int x = loc;
    #pragma unroll
    for (int o = 1; o < 32; o <<= 1) {
        int y = __shfl_up_sync(0xffffffffu, x, o);
        if (lane >= o) x += y;
    }
    __shared__ int wsums[32];
    if (lane == 31) wsums[warp] = x;
    __syncthreads();
    if (t < 32) {
        int y = wsums[t];
        #pragma unroll
        for (int o = 1; o < 32; o <<= 1) {
            int z = __shfl_up_sync(0xffffffffu, y, o);
            if (t >= o) y += z;
        }
        wsums[t] = y;
    }
    __syncthreads();
    int base = (warp ? wsums[warp - 1] : 0) + x - loc;   // exclusive prefix
    if (v0) g_rowidx[b * SEQ + base] = s0;
    if (v1) g_rowidx[b * SEQ + base + v0] = s1;
    if (t == 1023) g_count[b] = wsums[31];
}

// ---------------------------------------------------------------------------
// Kernel 2: zero g_score + expected_ctx.  grid(64), block(1024)
// ---------------------------------------------------------------------------
__global__ void zero_kernel(float* __restrict__ out_ec) {
    int i = blockIdx.x * blockDim.x + threadIdx.x;
    if (i < MROWS) g_score[i] = 0.0f;
    if (i < BATCH * DC) out_ec[i] = 0.0f;
}

// ---------------------------------------------------------------------------
// Kernel 3: TF32 mma.sync GEMM over COMPACTED rows.
// BM=128 BN=128 BK=32, 8 warps (2x4), warp tile 64x32,
// 3-stage cp.async pipeline, 2 CTAs/SM, gathered A, scattered score epilogue.
// grid(4 /*n*/, 512 /*b*16 mblocks*/), block(256)
// ---------------------------------------------------------------------------
#define A_WORDS (128*36)
#define B_WORDS (128*32)
#define STAGE_WORDS (A_WORDS + B_WORDS)
#define NSTAGE 3
#define SMEM_DYN (STAGE_WORDS * NSTAGE * 4)

__global__ __launch_bounds__(256, 2)
void gemm_kernel(const float* __restrict__ ctx,
                 const float* __restrict__ W2) {
    const int b     = blockIdx.y >> 4;
    const int brow0 = (blockIdx.y & 15) * 128;      // row offset within batch (compacted)
    const int count = g_count[b];
    if (brow0 >= count) return;

    extern __shared__ uint32_t smem[];
    __shared__ float s_qb[128];
    __shared__ float s_w2[128];
    __shared__ int   s_idx[128];

    const int n0   = blockIdx.x * 128;
    const int tid  = threadIdx.x;
    const int warp = tid >> 5;
    const int lane = tid & 31;
    const int wm   = warp >> 2;
    const int wn   = warp & 3;
    const int g    = lane >> 2;
    const int t    = lane & 3;

    if (tid < 128) {
        s_qb[tid] = g_qb[b * H + n0 + tid];
        s_w2[tid] = W2[n0 + tid];
        int rr = brow0 + tid;
        s_idx[tid] = g_rowidx[b * SEQ + (rr < count ? rr : count - 1)];
    }
    __syncthreads();

    const uint32_t smem_base = (uint32_t)__cvta_generic_to_shared(smem);

    // precompute per-thread A gather pointers / smem dsts (constant over kc)
    const float* aptr[4];
    uint32_t     adst[4];
    #pragma unroll
    for (int j = 0; j < 4; j++) {
        int idx = tid + j * 256;
        int m   = idx >> 3;
        int c   = idx & 7;
        aptr[j] = ctx + ((size_t)b * SEQ + s_idx[m]) * DC + c * 4;
        adst[j] = (uint32_t)(m * 36 + c * 4) * 4u;
    }
    const uint32_t* bsrc0 = g_Bt + (size_t)blockIdx.x * 32 * B_WORDS;

    auto issue = [&](int kc, int s) {
        uint32_t aBase = smem_base + (uint32_t)(s * STAGE_WORDS) * 4u;
        uint32_t bBase = aBase + A_WORDS * 4u;
        #pragma unroll
        for (int j = 0; j < 4; j++)
            cp_async16(aBase + adst[j], aptr[j] + kc * 32);
        const uint32_t* bsrc = bsrc0 + (size_t)kc * B_WORDS;
        #pragma unroll
        for (int j = 0; j < 4; j++) {
            int idx = tid + j * 256;
            cp_async16(bBase + (uint32_t)idx * 16u, bsrc + idx * 4);
        }
    };

    float acc[4][4][4];
    #pragma unroll
    for (int mt = 0; mt < 4; mt++)
        #pragma unroll
        for (int nt = 0; nt < 4; nt++)
            #pragma unroll
            for (int j = 0; j < 4; j++)
                acc[mt][nt][j] = 0.0f;

    issue(0, 0); cp_commit();
    issue(1, 1); cp_commit();

    const int aoff = (wm * 64 + g) * 36 + t;
    const int boff = (wn * 4 * 4) * 64 + lane * 2;

    for (int kc = 0; kc < 32; kc++) {
        const int s = kc % NSTAGE;
        cp_wait<NSTAGE - 2>();
        __syncthreads();

        if (kc + NSTAGE - 1 < 32) issue(kc + NSTAGE - 1, (kc + NSTAGE - 1) % NSTAGE);
        cp_commit();

        const uint32_t* sA = smem + s * STAGE_WORDS;
        const uint32_t* sB = sA + A_WORDS;

        #pragma unroll
        for (int ks = 0; ks < 4; ks++) {
            uint32_t af[4][4];
            #pragma unroll
            for (int mt = 0; mt < 4; mt++) {
                const uint32_t* base = sA + aoff + mt * 16 * 36 + ks * 8;
                af[mt][0] = base[0];
                af[mt][2] = base[4];
                af[mt][1] = base[8 * 36];
                af[mt][3] = base[8 * 36 + 4];
            }
            uint32_t bf[4][2];
            #pragma unroll
            for (int nt = 0; nt < 4; nt++) {
                const uint2 v = *(const uint2*)(sB + boff + nt * 4 * 64 + ks * 64);
                bf[nt][0] = v.x;
                bf[nt][1] = v.y;
            }
            #pragma unroll
            for (int mt = 0; mt < 4; mt++)
                #pragma unroll
                for (int nt = 0; nt < 4; nt++)
                    mma_tf32(acc[mt][nt], af[mt], bf[nt]);
        }
    }

    // --- fused epilogue: scatter g_score[orig] += sum_h W2[h]*tanh(acc+qb[h]) ---
    float w2v[4][2], qv[4][2];
    #pragma unroll
    for (int nt = 0; nt < 4; nt++)
        #pragma unroll
        for (int j = 0; j < 2; j++) {
            int hl = wn * 32 + nt * 8 + 2 * t + j;
            w2v[nt][j] = s_w2[hl];
            qv[nt][j]  = s_qb[hl];
        }

    #pragma unroll
    for (int mt = 0; mt < 4; mt++) {
        int rl = wm * 64 + mt * 16 + g;          // local row 0..127
        float s0 = 0.0f, s1 = 0.0f;
        #pragma unroll
        for (int nt = 0; nt < 4; nt++) {
            #pragma unroll
            for (int j = 0; j < 2; j++) {
                s0 += fast_tanh(acc[mt][nt][j]     + qv[nt][j]) * w2v[nt][j];
                s1 += fast_tanh(acc[mt][nt][2 + j] + qv[nt][j]) * w2v[nt][j];
            }
        }
        s0 += __shfl_xor_sync(0xffffffffu, s0, 1);
        s0 += __shfl_xor_sync(0xffffffffu, s0, 2);
        s1 += __shfl_xor_sync(0xffffffffu, s1, 1);
        s1 += __shfl_xor_sync(0xffffffffu, s1, 2);
        if (t == 0) {
            if (brow0 + rl < count)
                atomicAdd(&g_score[b * SEQ + s_idx[rl]], s0);
            if (brow0 + rl + 8 < count)
                atomicAdd(&g_score[b * SEQ + s_idx[rl + 8]], s1);
        }
    }
}

// ---------------------------------------------------------------------------
// Kernel 4: masked softmax per batch row. grid(32), block(1024)
// ---------------------------------------------------------------------------
__global__ void softmax_kernel(const int* __restrict__ mask,
                               const float* __restrict__ b2,
                               float* __restrict__ p_out) {
    int b   = blockIdx.x;
    int tid = threadIdx.x;
    __shared__ float red[32];

    const float bias = b2[0];
    int i0 = b * SEQ + tid;
    int i1 = i0 + 1024;
    float s0 = (mask[i0] != 0) ? g_score[i0] + bias : NEG_NUM;
    float s1 = (mask[i1] != 0) ? g_score[i1] + bias : NEG_NUM;

    float m = fmaxf(s0, s1);
    #pragma unroll
    for (int o = 16; o > 0; o >>= 1)
        m = fmaxf(m, __shfl_xor_sync(0xffffffffu, m, o));
    if ((tid & 31) == 0) red[tid >> 5] = m;
    __syncthreads();
    if (tid < 32) {
        float v = red[tid];
        #pragma unroll
        for (int o = 16; o > 0; o >>= 1)
            v = fmaxf(v, __shfl_xor_sync(0xffffffffu, v, o));
        red[tid] = v;
    }
    __syncthreads();
    m = red[0];
    __syncthreads();

    float e0 = __expf(s0 - m);
    float e1 = __expf(s1 - m);
    float sm = e0 + e1;
    #pragma unroll
    for (int o = 16; o > 0; o >>= 1)
        sm += __shfl_xor_sync(0xffffffffu, sm, o);
    if ((tid & 31) == 0) red[tid >> 5] = sm;
    __syncthreads();
    if (tid < 32) {
        float v = red[tid];
        #pragma unroll
        for (int o = 16; o > 0; o >>= 1)
            v += __shfl_xor_sync(0xffffffffu, v, o);
        red[tid] = v;
    }
    __syncthreads();
    float inv = 1.0f / red[0];

    p_out[i0] = e0 * inv;
    p_out[i1] = e1 * inv;
}

// ---------------------------------------------------------------------------
// Kernel 5: expected_ctx[b][d] = sum_s p[b][s]*ctx[b][s][d]
// grid(32 /*b*/, 8 /*s-chunk 256*/), block(256); thread owns 4 d's (float4).
// Rows with p==0 are skipped warp-uniformly (saves ~half the DRAM traffic).
// ---------------------------------------------------------------------------
__global__ __launch_bounds__(256)
void wsum_kernel(const float* __restrict__ ctx,
                 const float* __restrict__ p,
                 float* __restrict__ out_ec) {
    int b  = blockIdx.x;
    int s0 = blockIdx.y * 256;
    int d4 = threadIdx.x;                 // float4 index: d = d4*4

    __shared__ float sp[256];
    sp[threadIdx.x] = p[b * SEQ + s0 + threadIdx.x];
    __syncthreads();

    const float4* cptr = (const float4*)(ctx + ((size_t)b * SEQ + s0) * DC) + d4;
    float4 acc = make_float4(0.f, 0.f, 0.f, 0.f);
    #pragma unroll 4
    for (int s = 0; s < 256; s++) {
        float w = sp[s];
        if (w != 0.0f) {
            float4 v = cptr[(size_t)s * 256];
            acc.x += w * v.x;
            acc.y += w * v.y;
            acc.z += w * v.z;
            acc.w += w * v.w;
        }
    }
    float* o = out_ec + b * DC + d4 * 4;
    atomicAdd(o + 0, acc.x);
    atomicAdd(o + 1, acc.y);
    atomicAdd(o + 2, acc.z);
    atomicAdd(o + 3, acc.w);
}

// ---------------------------------------------------------------------------
// launch
// ---------------------------------------------------------------------------
extern "C" void kernel_launch(void* const* d_in, const int* in_sizes, int n_in,
                              void* d_out, int out_size) {
    const float* ctx   = (const float*)d_in[0];
    const float* query = (const float*)d_in[1];
    const float* W1    = (const float*)d_in[2];
    const float* b1    = (const float*)d_in[3];
    const float* W2    = (const float*)d_in[4];
    const float* b2    = (const float*)d_in[5];
    const int*   mask  = (const int*)d_in[6];

    float* out    = (float*)d_out;
    float* out_ec = out;
    float* out_p  = out + BATCH * DC;

    static bool attr_set = false;
    if (!attr_set) {
        cudaFuncSetAttribute(gemm_kernel,
                             cudaFuncAttributeMaxDynamicSharedMemorySize, SMEM_DYN);
        attr_set = true;
    }

    prep_kernel<<<BATCH, 512>>>(query, W1, b1);
    prepb_kernel<<<512, 1024>>>(W1);
    mask_scan_kernel<<<BATCH, 1024>>>(mask);
    zero_kernel<<<64, 1024>>>(out_ec);
    gemm_kernel<<<dim3(4, 512), 256, SMEM_DYN>>>(ctx, W2);
    softmax_kernel<<<BATCH, 1024>>>(mask, b2, out_p);
    wsum_kernel<<<dim3(BATCH, 8), 256>>>(ctx, out_p, out_ec);
}